// round 6
// baseline (speedup 1.0000x reference)
#include <cuda_runtime.h>
#include <cuda_bf16.h>
#include <math.h>
#include <stdint.h>

// ---------------------------------------------------------------------------
// Problem constants
// ---------------------------------------------------------------------------
#define T_STEPS 512
#define BATCH   256
#define INF     1024
#define HIDDEN  1024
#define WROW    (INF + HIDDEN)
#define NCLS    512
#define BH      (BATCH * HIDDEN)      // 262144
#define TB      (T_STEPS * BATCH)     // 131072
#define NCTAS   128                   // persistent recurrence grid

// ---------------------------------------------------------------------------
// Device-global scratch (allocation-free rule)
// ---------------------------------------------------------------------------
__device__ float g_A[(size_t)T_STEPS * BH];           // x-projection + b_ih (fp32)
__device__ float g_Hlast[BH];                          // final hidden state (fp32)
__device__ __nv_bfloat16 g_Xh[(size_t)TB * INF];      // X split hi
__device__ __nv_bfloat16 g_Xl[(size_t)TB * INF];      // X split lo
__device__ __nv_bfloat16 g_Hh[(size_t)T_STEPS * BH];  // H split hi
__device__ __nv_bfloat16 g_Hl[(size_t)T_STEPS * BH];  // H split lo
__device__ __nv_bfloat16 g_Wih_h[HIDDEN * WROW];      // W_ih hi (full, row stride WROW)
__device__ __nv_bfloat16 g_Wih_l[HIDDEN * WROW];
__device__ __nv_bfloat16 g_Who_h[NCLS * HIDDEN];      // W_ho hi
__device__ __nv_bfloat16 g_Who_l[NCLS * HIDDEN];
__device__ __nv_bfloat16 g_h0h[BH];                   // h0 split hi
__device__ __nv_bfloat16 g_h0l[BH];
__device__ unsigned g_cnt;                             // grid barrier count
__device__ unsigned g_gen;                             // grid barrier generation

// ---------------------------------------------------------------------------
// Portable PTX helpers (sm_80+ features only)
// ---------------------------------------------------------------------------
__device__ __forceinline__ uint32_t smem_to_u32(const void* p) {
    uint32_t a;
    asm("{ .reg .u64 t; cvta.to.shared.u64 t, %1; cvt.u32.u64 %0, t; }"
        : "=r"(a) : "l"(p));
    return a;
}

__device__ __forceinline__ void cp16(uint32_t dst, const void* src) {
    asm volatile("cp.async.cg.shared.global [%0], [%1], 16;"
                 :: "r"(dst), "l"(__cvta_generic_to_global(src)));
}
#define CP_COMMIT()  asm volatile("cp.async.commit_group;" ::: "memory")
#define CP_WAIT(n)   asm volatile("cp.async.wait_group %0;" :: "n"(n) : "memory")

#define LDSM4(r0, r1, r2, r3, addr) \
    asm volatile("ldmatrix.sync.aligned.m8n8.x4.shared.b16 {%0,%1,%2,%3}, [%4];" \
                 : "=r"(r0), "=r"(r1), "=r"(r2), "=r"(r3) : "r"(addr))
#define LDSM2(r0, r1, addr) \
    asm volatile("ldmatrix.sync.aligned.m8n8.x2.shared.b16 {%0,%1}, [%2];" \
                 : "=r"(r0), "=r"(r1) : "r"(addr))

// D[16x8] += A[16x16] * B[16x8]^(col)  -- bf16 in, fp32 accum
__device__ __forceinline__ void mma_bf16(float* c, const uint32_t* a, const uint32_t* b) {
    asm volatile(
        "mma.sync.aligned.m16n8k16.row.col.f32.bf16.bf16.f32 "
        "{%0,%1,%2,%3}, {%4,%5,%6,%7}, {%8,%9}, {%0,%1,%2,%3};"
        : "+f"(c[0]), "+f"(c[1]), "+f"(c[2]), "+f"(c[3])
        : "r"(a[0]), "r"(a[1]), "r"(a[2]), "r"(a[3]), "r"(b[0]), "r"(b[1]));
}

// ---------------------------------------------------------------------------
// fp32 -> (hi, lo) bf16 split
// ---------------------------------------------------------------------------
__device__ __forceinline__ void split1(float v, __nv_bfloat16& h, __nv_bfloat16& l) {
    h = __float2bfloat16(v);
    l = __float2bfloat16(v - __bfloat162float(h));
}

__global__ void split_mat(const float* __restrict__ src, long lda, long rows, long cols,
                          __nv_bfloat16* __restrict__ hi, __nv_bfloat16* __restrict__ lo)
{
    long n4 = rows * cols / 4;
    for (long i = blockIdx.x * (long)blockDim.x + threadIdx.x; i < n4;
         i += (long)gridDim.x * blockDim.x) {
        long e = i * 4;
        long r = e / cols, c = e % cols;
        float4 v = *(const float4*)(src + r * lda + c);
        __nv_bfloat16 h0, h1, h2, h3, l0, l1, l2, l3;
        split1(v.x, h0, l0); split1(v.y, h1, l1);
        split1(v.z, h2, l2); split1(v.w, h3, l3);
        __nv_bfloat162 t;
        t.x = h0; t.y = h1; *(__nv_bfloat162*)(hi + e)     = t;
        t.x = h2; t.y = h3; *(__nv_bfloat162*)(hi + e + 2) = t;
        t.x = l0; t.y = l1; *(__nv_bfloat162*)(lo + e)     = t;
        t.x = l2; t.y = l3; *(__nv_bfloat162*)(lo + e + 2) = t;
    }
}

// ---------------------------------------------------------------------------
// mma.sync bf16x3 GEMM (phases 1 & 3, unchanged from R5 -- near HMMA roofline)
// ---------------------------------------------------------------------------
#define ROWB   80
#define G_MAT  (128 * ROWB)
#define G_STG  (4 * G_MAT)
#define G_SMEM (2 * G_STG)           // 81920

__global__ void __launch_bounds__(256, 1)
gemm_mma_x3(const __nv_bfloat16* __restrict__ Ah, const __nv_bfloat16* __restrict__ Al, long lda,
            const __nv_bfloat16* __restrict__ Bh, const __nv_bfloat16* __restrict__ Bl, long ldb,
            const float* __restrict__ bias, float* __restrict__ C, long ldc, int K)
{
    extern __shared__ char smem[];
    const uint32_t sb = smem_to_u32(smem);
    const int tid = threadIdx.x, lane = tid & 31, wid = tid >> 5;
    const int wm = wid & 3, wn = wid >> 2;
    const long bm = (long)blockIdx.y * 128;
    const long bn = (long)blockIdx.x * 128;

    float c[2][8][4];
#pragma unroll
    for (int m = 0; m < 2; m++)
#pragma unroll
        for (int n = 0; n < 8; n++)
#pragma unroll
            for (int j = 0; j < 4; j++) c[m][n][j] = 0.0f;

    const uint32_t a_rb = (uint32_t)(lane & 15) * ROWB + (uint32_t)(lane >> 4) * 16;
    const uint32_t b_rb = (uint32_t)(lane & 7) * ROWB + (uint32_t)((lane >> 3) & 1) * 16;

    auto load_chunk = [&](int kc, int stage) {
        uint32_t base = sb + stage * G_STG;
#pragma unroll
        for (int it = 0; it < 2; it++) {
            int u = tid + it * 256;
            int row = u >> 2, seg = u & 3;
            uint32_t so = row * ROWB + seg * 16;
            long ga = (bm + row) * lda + kc + seg * 8;
            long gb = (bn + row) * ldb + kc + seg * 8;
            cp16(base + so,             Ah + ga);
            cp16(base + G_MAT + so,     Al + ga);
            cp16(base + 2 * G_MAT + so, Bh + gb);
            cp16(base + 3 * G_MAT + so, Bl + gb);
        }
    };

    const int nchunk = K >> 5;
    load_chunk(0, 0);
    CP_COMMIT();

    for (int ch = 0; ch < nchunk; ch++) {
        if (ch + 1 < nchunk) {
            load_chunk((ch + 1) << 5, (ch + 1) & 1);
            CP_COMMIT();
            CP_WAIT(1);
        } else {
            CP_WAIT(0);
        }
        __syncthreads();

        const uint32_t base = sb + (ch & 1) * G_STG;
#pragma unroll
        for (int k16 = 0; k16 < 2; k16++) {
            const uint32_t kb = k16 * 32;
            uint32_t ah[2][4], al[2][4], bh[8][2], bl[8][2];
#pragma unroll
            for (int m = 0; m < 2; m++) {
                uint32_t ra = base + (uint32_t)(wm * 32 + m * 16) * ROWB + kb + a_rb;
                LDSM4(ah[m][0], ah[m][1], ah[m][2], ah[m][3], ra);
                LDSM4(al[m][0], al[m][1], al[m][2], al[m][3], ra + G_MAT);
            }
#pragma unroll
            for (int n = 0; n < 8; n++) {
                uint32_t rb = base + 2 * G_MAT + (uint32_t)(wn * 64 + n * 8) * ROWB + kb + b_rb;
                LDSM2(bh[n][0], bh[n][1], rb);
                LDSM2(bl[n][0], bl[n][1], rb + G_MAT);
            }
#pragma unroll
            for (int m = 0; m < 2; m++)
#pragma unroll
                for (int n = 0; n < 8; n++) {
                    mma_bf16(c[m][n], ah[m], bh[n]);
                    mma_bf16(c[m][n], al[m], bh[n]);
                    mma_bf16(c[m][n], ah[m], bl[n]);
                }
        }
        __syncthreads();
    }

#pragma unroll
    for (int m = 0; m < 2; m++) {
        long r0 = bm + wm * 32 + m * 16 + (lane >> 2);
        long r1 = r0 + 8;
#pragma unroll
        for (int n = 0; n < 8; n++) {
            long col = bn + wn * 64 + n * 8 + (lane & 3) * 2;
            float bx = bias[col], by = bias[col + 1];
            float2 v0 = { c[m][n][0] + bx, c[m][n][1] + by };
            float2 v1 = { c[m][n][2] + bx, c[m][n][3] + by };
            *(float2*)(C + r0 * ldc + col) = v0;
            *(float2*)(C + r1 * ldc + col) = v1;
        }
    }
}

// ---------------------------------------------------------------------------
// Grid-wide barrier (replay-safe, monotonic generation)
// ---------------------------------------------------------------------------
__device__ __forceinline__ void grid_bar(unsigned& lgen)
{
    __syncthreads();
    if (threadIdx.x == 0) {
        __threadfence();
        if (atomicAdd(&g_cnt, 1u) == NCTAS - 1) {
            atomicExch(&g_cnt, 0u);
            __threadfence();
            atomicAdd(&g_gen, 1u);
        } else {
            while (*(volatile unsigned*)&g_gen == lgen) { __nanosleep(32); }
            __threadfence();
        }
        lgen++;
    }
    __syncthreads();
}

// ---------------------------------------------------------------------------
// Persistent recurrence v3:  h_t = tanh(g_A[t] + h_{t-1} @ W_h^T)
// 128 CTAs x 256 thr; CTA tile 64(M=batch) x 32(N=hidden); warps 4M x 2N.
// BOTH W_h tiles resident in smem (hi+lo = 129 KB).  Streams only h_{t-1}
// hi/lo, BK=128 (8 chunks/step), double-buffered, pipelined ldmatrix.
// ---------------------------------------------------------------------------
#define A_ROWB     272                        // 256B data + 16 pad
#define RB_ROWB    2064                       // 2048B data + 16 pad
#define RB_SZ      (32 * RB_ROWB)             // 66048 per matrix
#define R_OFF_BL   RB_SZ
#define R_OFF_STG  (2 * RB_SZ)                // 132096
#define RA_SZ      (64 * A_ROWB)              // 17408 per matrix
#define R_STG      (2 * RA_SZ)                // 34816 (Ah | Al)
#define R_SMEM     (R_OFF_STG + 2 * R_STG)    // 201728

__global__ void __launch_bounds__(256, 1)
rnn_recur()
{
    extern __shared__ char smem[];
    const uint32_t sb = smem_to_u32(smem);
    const int tid = threadIdx.x, lane = tid & 31, wid = tid >> 5;
    const int wm = wid & 3, wn = wid >> 2;        // 4 x 2 warp grid
    const int bm = (blockIdx.x >> 5) * 64;        // 4 M-tiles
    const int bn = (blockIdx.x & 31) * 32;        // 32 N-tiles

    const uint32_t a_rb = (uint32_t)(lane & 15) * A_ROWB + (uint32_t)(lane >> 4) * 16;
    const uint32_t b_rb = (uint32_t)(lane & 7) * RB_ROWB + (uint32_t)((lane >> 3) & 1) * 16;

    // ---- Resident W_h tiles: 32 rows x 1024 bf16, hi then lo (4096 units each)
    for (int u = tid; u < 4096; u += 256) {
        int row = u >> 7, seg = u & 127;
        size_t g = (size_t)(bn + row) * WROW + INF + seg * 8;
        cp16(sb + row * RB_ROWB + seg * 16,            g_Wih_h + g);
        cp16(sb + R_OFF_BL + row * RB_ROWB + seg * 16, g_Wih_l + g);
    }
    CP_COMMIT();

    // A stream load map: per matrix 64 rows x 16 segs = 1024 units (4/thread)
    const int sa_row = tid >> 2, sa_seg4 = (tid & 3) * 4;   // 4 consecutive segs

    unsigned lgen = *(volatile unsigned*)&g_gen;

    const int warp_base = wm * 16;              // A rows for this warp
    const uint32_t bboff = (uint32_t)(wn * 16) * RB_ROWB;

    for (int t = 0; t < T_STEPS; t++) {
        const __nv_bfloat16* hh = (t == 0) ? g_h0h : (g_Hh + (size_t)(t - 1) * BH);
        const __nv_bfloat16* hl = (t == 0) ? g_h0l : (g_Hl + (size_t)(t - 1) * BH);
        const size_t ob = (size_t)t * BH;

        // Prefetch epilogue pre-activation (independent of h_{t-1})
        const int er0 = bm + wm * 16 + (lane >> 2);
        const int ec0 = bn + wn * 16 + (lane & 3) * 2;
        float2 pre[2][2];
#pragma unroll
        for (int n = 0; n < 2; n++) {
            pre[n][0] = *(const float2*)(g_A + ob + (size_t)er0       * HIDDEN + ec0 + n * 8);
            pre[n][1] = *(const float2*)(g_A + ob + (size_t)(er0 + 8) * HIDDEN + ec0 + n * 8);
        }

        float c[2][4];
#pragma unroll
        for (int n = 0; n < 2; n++)
#pragma unroll
            for (int j = 0; j < 4; j++) c[n][j] = 0.0f;

        auto load_chunk = [&](int kc, int stage) {
            uint32_t base = sb + R_OFF_STG + stage * R_STG;
            uint32_t so = sa_row * A_ROWB + sa_seg4 * 16;
            size_t g = (size_t)(bm + sa_row) * HIDDEN + kc + sa_seg4 * 8;
#pragma unroll
            for (int s = 0; s < 4; s++) {
                cp16(base + so + s * 16,         hh + g + s * 8);
                cp16(base + RA_SZ + so + s * 16, hl + g + s * 8);
            }
        };

        load_chunk(0, 0);
        CP_COMMIT();

        for (int ch = 0; ch < 8; ch++) {          // BK = 128
            if (ch + 1 < 8) {
                load_chunk((ch + 1) << 7, (ch + 1) & 1);
                CP_COMMIT();
                CP_WAIT(1);
            } else {
                CP_WAIT(0);
            }
            __syncthreads();

            const uint32_t abase = sb + R_OFF_STG + (ch & 1) * R_STG
                                   + (uint32_t)warp_base * A_ROWB + a_rb;
            const uint32_t bbase = sb + bboff + (uint32_t)(ch << 8) + b_rb;

            // Software-pipelined k16 loop (8 iters), double-buffered fragments
            uint32_t ah[2][4], al[2][4], bh[2][2][2], bl[2][2][2];

#define R_LDSM(k16, buf) do { \
        uint32_t _ra = abase + (uint32_t)((k16) * 32); \
        LDSM4(ah[buf][0], ah[buf][1], ah[buf][2], ah[buf][3], _ra); \
        LDSM4(al[buf][0], al[buf][1], al[buf][2], al[buf][3], _ra + RA_SZ); \
        uint32_t _rb0 = bbase + (uint32_t)((k16) * 32); \
        LDSM2(bh[buf][0][0], bh[buf][0][1], _rb0); \
        LDSM2(bl[buf][0][0], bl[buf][0][1], _rb0 + R_OFF_BL); \
        uint32_t _rb1 = _rb0 + 8 * RB_ROWB; \
        LDSM2(bh[buf][1][0], bh[buf][1][1], _rb1); \
        LDSM2(bl[buf][1][0], bl[buf][1][1], _rb1 + R_OFF_BL); \
    } while (0)

            R_LDSM(0, 0);
#pragma unroll
            for (int k16 = 0; k16 < 8; k16++) {
                if (k16 < 7) R_LDSM(k16 + 1, (k16 + 1) & 1);
                const int b = k16 & 1;
#pragma unroll
                for (int n = 0; n < 2; n++) {
                    mma_bf16(c[n], ah[b], bh[b][n]);
                    mma_bf16(c[n], al[b], bh[b][n]);
                    mma_bf16(c[n], ah[b], bl[b][n]);
                }
            }
#undef R_LDSM
            __syncthreads();
        }

        // Epilogue: tanh(acc + pre), split to bf16 hi/lo
        {
            const int r0 = er0, r1 = er0 + 8;
#pragma unroll
            for (int n = 0; n < 2; n++) {
                const int col = ec0 + n * 8;
                float h00 = tanhf(c[n][0] + pre[n][0].x);
                float h01 = tanhf(c[n][1] + pre[n][0].y);
                float h10 = tanhf(c[n][2] + pre[n][1].x);
                float h11 = tanhf(c[n][3] + pre[n][1].y);

                __nv_bfloat16 hb, lb;
                __nv_bfloat162 th, tl;
                split1(h00, hb, lb); th.x = hb; tl.x = lb;
                split1(h01, hb, lb); th.y = hb; tl.y = lb;
                *(__nv_bfloat162*)(g_Hh + ob + (size_t)r0 * HIDDEN + col) = th;
                *(__nv_bfloat162*)(g_Hl + ob + (size_t)r0 * HIDDEN + col) = tl;
                split1(h10, hb, lb); th.x = hb; tl.x = lb;
                split1(h11, hb, lb); th.y = hb; tl.y = lb;
                *(__nv_bfloat162*)(g_Hh + ob + (size_t)r1 * HIDDEN + col) = th;
                *(__nv_bfloat162*)(g_Hl + ob + (size_t)r1 * HIDDEN + col) = tl;

                if (t == T_STEPS - 1) {
                    float2 f0 = { h00, h01 }, f1 = { h10, h11 };
                    *(float2*)(g_Hlast + (size_t)r0 * HIDDEN + col) = f0;
                    *(float2*)(g_Hlast + (size_t)r1 * HIDDEN + col) = f1;
                }
            }
        }

        grid_bar(lgen);
    }
}

// ---------------------------------------------------------------------------
// In-place softmax over rows of 512 floats
// ---------------------------------------------------------------------------
__global__ void softmax512(float* __restrict__ O)
{
    __shared__ float red[4];
    long row = blockIdx.x;
    float4* p = (float4*)(O + row * (long)NCLS);
    float4 v = p[threadIdx.x];

    float m = fmaxf(fmaxf(v.x, v.y), fmaxf(v.z, v.w));
#pragma unroll
    for (int o = 16; o > 0; o >>= 1)
        m = fmaxf(m, __shfl_xor_sync(0xffffffffu, m, o));
    int warp = threadIdx.x >> 5;
    if ((threadIdx.x & 31) == 0) red[warp] = m;
    __syncthreads();
    m = fmaxf(fmaxf(red[0], red[1]), fmaxf(red[2], red[3]));

    float4 e;
    e.x = __expf(v.x - m);
    e.y = __expf(v.y - m);
    e.z = __expf(v.z - m);
    e.w = __expf(v.w - m);
    float s = e.x + e.y + e.z + e.w;
#pragma unroll
    for (int o = 16; o > 0; o >>= 1)
        s += __shfl_xor_sync(0xffffffffu, s, o);
    __syncthreads();
    if ((threadIdx.x & 31) == 0) red[warp] = s;
    __syncthreads();
    s = red[0] + red[1] + red[2] + red[3];

    float inv = 1.0f / s;
    e.x *= inv; e.y *= inv; e.z *= inv; e.w *= inv;
    p[threadIdx.x] = e;
}

// ---------------------------------------------------------------------------
// Launch (9 graph nodes)
// ---------------------------------------------------------------------------
extern "C" void kernel_launch(void* const* d_in, const int* in_sizes, int n_in,
                              void* d_out, int out_size)
{
    const float* x    = (const float*)d_in[0];
    const float* h0   = (const float*)d_in[1];
    const float* W_ih = (const float*)d_in[2];
    const float* b_ih = (const float*)d_in[3];
    const float* W_ho = (const float*)d_in[4];
    const float* b_ho = (const float*)d_in[5];
    float*       out  = (float*)d_out;

    float *pA, *pHlast;
    __nv_bfloat16 *pXh, *pXl, *pHh, *pHl, *pWih_h, *pWih_l, *pWoh, *pWol, *ph0h, *ph0l;
    cudaGetSymbolAddress((void**)&pA,     g_A);
    cudaGetSymbolAddress((void**)&pHlast, g_Hlast);
    cudaGetSymbolAddress((void**)&pXh,    g_Xh);
    cudaGetSymbolAddress((void**)&pXl,    g_Xl);
    cudaGetSymbolAddress((void**)&pHh,    g_Hh);
    cudaGetSymbolAddress((void**)&pHl,    g_Hl);
    cudaGetSymbolAddress((void**)&pWih_h, g_Wih_h);
    cudaGetSymbolAddress((void**)&pWih_l, g_Wih_l);
    cudaGetSymbolAddress((void**)&pWoh,   g_Who_h);
    cudaGetSymbolAddress((void**)&pWol,   g_Who_l);
    cudaGetSymbolAddress((void**)&ph0h,   g_h0h);
    cudaGetSymbolAddress((void**)&ph0l,   g_h0l);

    cudaFuncSetAttribute(gemm_mma_x3,
                         cudaFuncAttributeMaxDynamicSharedMemorySize, G_SMEM);
    cudaFuncSetAttribute(rnn_recur,
                         cudaFuncAttributeMaxDynamicSharedMemorySize, R_SMEM);

    // Splits: X, W_ih (full), W_ho, h0
    split_mat<<<4096, 256>>>(x,    INF,    TB,     INF,    pXh,    pXl);
    split_mat<<<512,  256>>>(W_ih, WROW,   HIDDEN, WROW,   pWih_h, pWih_l);
    split_mat<<<256,  256>>>(W_ho, HIDDEN, NCLS,   HIDDEN, pWoh,   pWol);
    split_mat<<<128,  256>>>(h0,   HIDDEN, BATCH,  HIDDEN, ph0h,   ph0l);

    // Phase 1: g_A = X @ Wx^T + b_ih
    {
        dim3 grid(HIDDEN / 128, TB / 128);   // (8, 1024)
        gemm_mma_x3<<<grid, 256, G_SMEM>>>(pXh, pXl, INF,
                                           pWih_h, pWih_l, WROW,
                                           b_ih, pA, HIDDEN, INF);
    }

    // Phase 2: persistent recurrence (mma.sync bf16x3, W fully resident, BK=128)
    rnn_recur<<<NCTAS, 256, R_SMEM>>>();

    // Phase 3: out = H @ W_ho^T + b_ho, then in-place softmax
    {
        dim3 grid(NCLS / 128, TB / 128);     // (4, 1024)
        gemm_mma_x3<<<grid, 256, G_SMEM>>>(pHh, pHl, HIDDEN,
                                           pWoh, pWol, HIDDEN,
                                           b_ho, out, NCLS, HIDDEN);
        softmax512<<<TB, 128>>>(out);
    }

    // h_last
    cudaMemcpyAsync(out + (long)TB * NCLS, pHlast,
                    (size_t)BH * sizeof(float), cudaMemcpyDeviceToDevice);
}